// round 9
// baseline (speedup 1.0000x reference)
#include <cuda_runtime.h>
#include <cuda_bf16.h>
#include <cstdint>
#include <cstddef>

#define D 128
#define EPS_BN 1e-5f
#define MAX_NODES 100000
#define CAP 96
#define BSTRIDE 136      // B smem row stride in bf16 (68 words: conflict-free)
#define ASTRIDE 72       // A smem row stride in bf16 (36 words: conflict-free)

// ---------------- scratch (__device__ globals; allocation-free rule) --------
__device__ float  g_hA[(size_t)MAX_NODES * D];
__device__ float  g_hB[(size_t)MAX_NODES * D];
__device__ float2 g_edges[(size_t)MAX_NODES * CAP];
__device__ int    g_cnt[MAX_NODES];
__device__ float  g_stats[4 * D];
__device__ __nv_bfloat16 g_wt_hi[3][D * D];   // W^T split-hi, [n][k]
__device__ __nv_bfloat16 g_wt_lo[3][D * D];   // W^T split-lo, [n][k]

// ---------------- f32x2 helpers ---------------------------------------------
__device__ __forceinline__ unsigned long long pack2s(float v) {
    unsigned long long r;
    asm("mov.b64 %0, {%1, %1};" : "=l"(r) : "f"(v));
    return r;
}
__device__ __forceinline__ void unpack2(unsigned long long v, float& lo, float& hi) {
    asm("mov.b64 {%0, %1}, %2;" : "=f"(lo), "=f"(hi) : "l"(v));
}
__device__ __forceinline__ unsigned long long ffma2(
    unsigned long long a, unsigned long long b, unsigned long long c) {
    unsigned long long d;
    asm("fma.rn.f32x2 %0, %1, %2, %3;" : "=l"(d) : "l"(a), "l"(b), "l"(c));
    return d;
}

// ---------------- prep: zero cnt/stats + W transpose/split (one launch) -----
__global__ void prep_kernel(const float* __restrict__ W0, const float* __restrict__ W1,
                            const float* __restrict__ W2,
                            __nv_bfloat16* __restrict__ th, __nv_bfloat16* __restrict__ tl,
                            int* __restrict__ cnt, float* __restrict__ stats, int n) {
    int i = blockIdx.x * blockDim.x + threadIdx.x;
    int stride = gridDim.x * blockDim.x;
    for (int j = i; j < n; j += stride) cnt[j] = 0;
    if (i < 4 * D) stats[i] = 0.0f;
    for (int j = i; j < 3 * D * D; j += stride) {
        int layer = j >> 14;
        int idx   = j & (D * D - 1);
        const float* W = (layer == 0) ? W0 : (layer == 1) ? W1 : W2;
        int nn = idx & 127, k = idx >> 7;
        float v = W[idx];
        __nv_bfloat16 h = __float2bfloat16(v);
        float r = v - __bfloat162float(h);
        th[layer * D * D + nn * D + k] = h;
        tl[layer * D * D + nn * D + k] = __float2bfloat16(r);
    }
}

// ---------------- scatter edges into per-row buckets ------------------------
__global__ void scatter_kernel(const int* __restrict__ row, const int* __restrict__ col,
                               const float* __restrict__ w, float2* __restrict__ edges,
                               int* __restrict__ cnt, int nedges) {
    int e = blockIdx.x * blockDim.x + threadIdx.x;
    if (e >= nedges) return;
    int r = row[e];
    int slot = atomicAdd(&cnt[r], 1);
    if (slot < CAP)
        edges[(size_t)r * CAP + slot] = make_float2(__int_as_float(col[e]), w[e]);
}

// ---------------- warp-tile MMA ----------------------------------------------
__device__ __forceinline__ void mma16816(float* c, const uint32_t* a, const uint32_t* b) {
    asm volatile(
        "mma.sync.aligned.m16n8k16.row.col.f32.bf16.bf16.f32 "
        "{%0,%1,%2,%3}, {%4,%5,%6,%7}, {%8,%9}, {%0,%1,%2,%3};"
        : "+f"(c[0]), "+f"(c[1]), "+f"(c[2]), "+f"(c[3])
        : "r"(a[0]), "r"(a[1]), "r"(a[2]), "r"(a[3]), "r"(b[0]), "r"(b[1]));
}

// truncation split of 2 floats -> (hi bf16x2, lo bf16x2)
__device__ __forceinline__ void split2(float vx, float vy, uint32_t& hi2, uint32_t& lo2) {
    uint32_t bx = __float_as_uint(vx) & 0xffff0000u;
    uint32_t by = __float_as_uint(vy) & 0xffff0000u;
    hi2 = __byte_perm(bx, by, 0x7632);
    float lx = vx - __uint_as_float(bx);
    float ly = vy - __uint_as_float(by);
    __nv_bfloat162 l = __floats2bfloat162_rn(lx, ly);
    lo2 = *(uint32_t*)&l;
}

// GEMM: Y = act(X) @ W + b; act = relu(bn) from raw column stats in-kernel.
__global__ __launch_bounds__(256, 2) void gemm_mma_kernel(
    const float* __restrict__ X,
    const __nv_bfloat16* __restrict__ Wt_hi, const __nv_bfloat16* __restrict__ Wt_lo,
    const float* __restrict__ bias,
    const float* __restrict__ stats,
    const float* __restrict__ gamma, const float* __restrict__ beta,
    float inv_n,
    float* __restrict__ Y, int nrows, int use_bn)
{
    extern __shared__ __align__(16) char dsm[];
    float* s_scale = (float*)dsm;
    float* s_shift = s_scale + D;
    __nv_bfloat16* Bh = (__nv_bfloat16*)(dsm + 1024);
    __nv_bfloat16* Bl = Bh + 128 * BSTRIDE;
    __nv_bfloat16* Ah = Bl + 128 * BSTRIDE;
    __nv_bfloat16* Al = Ah + 128 * ASTRIDE;

    int t = threadIdx.x, lane = t & 31, wid = t >> 5;
    int row0 = blockIdx.x * 128;
    int g = lane >> 2, tg = lane & 3;

    if (use_bn && t < D) {
        float m   = stats[t] * inv_n;
        float var = stats[D + t] * inv_n - m * m;
        float rs  = rsqrtf(var + EPS_BN);
        float sc  = gamma[t] * rs;
        s_scale[t] = sc;
        s_shift[t] = beta[t] - m * sc;
    }

    for (int i = t; i < 2048; i += 256) {
        int n  = i >> 4;
        int c8 = i & 15;
        *(uint4*)&Bh[n * BSTRIDE + c8 * 8] = *(const uint4*)&Wt_hi[n * D + c8 * 8];
        *(uint4*)&Bl[n * BSTRIDE + c8 * 8] = *(const uint4*)&Wt_lo[n * D + c8 * 8];
    }

    int m0 = (wid & 1) * 64;
    int n0 = (wid >> 1) * 32;

    float acc[4][4][4];
#pragma unroll
    for (int mt = 0; mt < 4; mt++)
#pragma unroll
        for (int nt = 0; nt < 4; nt++)
#pragma unroll
            for (int j = 0; j < 4; j++) acc[mt][nt][j] = 0.0f;

    __syncthreads();

#pragma unroll
    for (int kh = 0; kh < 2; kh++) {
        for (int i = t; i < 2048; i += 256) {
            int r  = i >> 4;
            int f4 = i & 15;
            int col0 = kh * 64 + f4 * 4;
            int row = row0 + r;
            float4 v = make_float4(0.f, 0.f, 0.f, 0.f);
            if (row < nrows) {
                v = *(const float4*)&X[(size_t)row * D + col0];
                if (use_bn) {
                    v.x = fmaxf(fmaf(v.x, s_scale[col0 + 0], s_shift[col0 + 0]), 0.0f);
                    v.y = fmaxf(fmaf(v.y, s_scale[col0 + 1], s_shift[col0 + 1]), 0.0f);
                    v.z = fmaxf(fmaf(v.z, s_scale[col0 + 2], s_shift[col0 + 2]), 0.0f);
                    v.w = fmaxf(fmaf(v.w, s_scale[col0 + 3], s_shift[col0 + 3]), 0.0f);
                }
            }
            uint2 ph, pl;
            split2(v.x, v.y, ph.x, pl.x);
            split2(v.z, v.w, ph.y, pl.y);
            *(uint2*)&Ah[r * ASTRIDE + f4 * 4] = ph;
            *(uint2*)&Al[r * ASTRIDE + f4 * 4] = pl;
        }
        __syncthreads();

#pragma unroll
        for (int pass = 0; pass < 3; pass++) {
            const __nv_bfloat16* Asm = (pass < 2) ? Ah : Al;
            const __nv_bfloat16* Bsm = (pass == 1) ? Bl : Bh;
#pragma unroll
            for (int ks = 0; ks < 4; ks++) {
                uint32_t a[4][4];
#pragma unroll
                for (int mt = 0; mt < 4; mt++) {
                    const uint32_t* p0 =
                        (const uint32_t*)&Asm[(m0 + mt * 16 + g) * ASTRIDE] + ks * 8 + tg;
                    const uint32_t* p1 =
                        (const uint32_t*)&Asm[(m0 + mt * 16 + g + 8) * ASTRIDE] + ks * 8 + tg;
                    a[mt][0] = p0[0];
                    a[mt][1] = p1[0];
                    a[mt][2] = p0[4];
                    a[mt][3] = p1[4];
                }
                uint32_t b[4][2];
#pragma unroll
                for (int nt = 0; nt < 4; nt++) {
                    const uint32_t* pb =
                        (const uint32_t*)&Bsm[(n0 + nt * 8 + g) * BSTRIDE]
                        + kh * 32 + ks * 8 + tg;
                    b[nt][0] = pb[0];
                    b[nt][1] = pb[4];
                }
#pragma unroll
                for (int mt = 0; mt < 4; mt++)
#pragma unroll
                    for (int nt = 0; nt < 4; nt++)
                        mma16816(acc[mt][nt], a[mt], b[nt]);
            }
        }
        __syncthreads();
    }

    float2 bv[4];
#pragma unroll
    for (int nt = 0; nt < 4; nt++) {
        int cidx = n0 + nt * 8 + tg * 2;
        bv[nt] = *(const float2*)&bias[cidx];
    }
#pragma unroll
    for (int mt = 0; mt < 4; mt++) {
        int ra = row0 + m0 + mt * 16 + g;
        int rb = ra + 8;
#pragma unroll
        for (int nt = 0; nt < 4; nt++) {
            int cidx = n0 + nt * 8 + tg * 2;
            if (ra < nrows) {
                float2 o = make_float2(acc[mt][nt][0] + bv[nt].x,
                                       acc[mt][nt][1] + bv[nt].y);
                *(float2*)&Y[(size_t)ra * D + cidx] = o;
            }
            if (rb < nrows) {
                float2 o = make_float2(acc[mt][nt][2] + bv[nt].x,
                                       acc[mt][nt][3] + bv[nt].y);
                *(float2*)&Y[(size_t)rb * D + cidx] = o;
            }
        }
    }
}

// ---------------- SpMM: warp per row, uniform edge loads, f32x2 accumulate --
__global__ __launch_bounds__(256) void spmm_kernel(
    const int* __restrict__ cnt, const float2* __restrict__ edges,
    const float* __restrict__ H, float* __restrict__ out,
    float* __restrict__ stats, int nrows, int with_stats)
{
    __shared__ float s_st[2 * D];

    int lane  = threadIdx.x & 31;
    int warp  = blockIdx.x * 8 + (threadIdx.x >> 5);
    int nwarp = gridDim.x * 8;

    if (with_stats) {
        for (int i = threadIdx.x; i < 2 * D; i += 256) s_st[i] = 0.0f;
        __syncthreads();
    }

    float4 ssum = make_float4(0.f, 0.f, 0.f, 0.f);
    float4 ssq  = make_float4(0.f, 0.f, 0.f, 0.f);

    for (int r = warp; r < nrows; r += nwarp) {
        int deg = __ldg(&cnt[r]);
        const float2* bucket = &edges[(size_t)r * CAP];
        unsigned long long a01 = 0ULL, a23 = 0ULL;

        for (int base = 0; base < deg; base += 8) {
            int nn = deg - base;            // uniform across warp
            unsigned long long w2[8];
            ulonglong2 v[8];
#pragma unroll
            for (int jj = 0; jj < 8; jj++) {
                if (jj < nn) {
                    float2 e = __ldg(&bucket[base + jj]);   // broadcast load
                    int c = __float_as_int(e.x);
                    w2[jj] = pack2s(e.y);
                    v[jj] = *(const ulonglong2*)&H[(size_t)c * D + lane * 4];
                } else {
                    w2[jj] = 0ULL;
                    v[jj] = make_ulonglong2(0ULL, 0ULL);
                }
            }
#pragma unroll
            for (int jj = 0; jj < 8; jj++) {
                a01 = ffma2(v[jj].x, w2[jj], a01);
                a23 = ffma2(v[jj].y, w2[jj], a23);
            }
        }

        float4 acc;
        unpack2(a01, acc.x, acc.y);
        unpack2(a23, acc.z, acc.w);
        *(float4*)&out[(size_t)r * D + lane * 4] = acc;

        if (with_stats) {
            ssum.x += acc.x; ssum.y += acc.y; ssum.z += acc.z; ssum.w += acc.w;
            ssq.x += acc.x * acc.x; ssq.y += acc.y * acc.y;
            ssq.z += acc.z * acc.z; ssq.w += acc.w * acc.w;
        }
    }

    if (with_stats) {
        atomicAdd(&s_st[lane * 4 + 0], ssum.x);
        atomicAdd(&s_st[lane * 4 + 1], ssum.y);
        atomicAdd(&s_st[lane * 4 + 2], ssum.z);
        atomicAdd(&s_st[lane * 4 + 3], ssum.w);
        atomicAdd(&s_st[D + lane * 4 + 0], ssq.x);
        atomicAdd(&s_st[D + lane * 4 + 1], ssq.y);
        atomicAdd(&s_st[D + lane * 4 + 2], ssq.z);
        atomicAdd(&s_st[D + lane * 4 + 3], ssq.w);
        __syncthreads();
        for (int i = threadIdx.x; i < 2 * D; i += 256)
            atomicAdd(&stats[i], s_st[i]);
    }
}

// ---------------- launch -----------------------------------------------------
extern "C" void kernel_launch(void* const* d_in, const int* in_sizes, int n_in,
                              void* d_out, int out_size)
{
    const float* x   = (const float*)d_in[0];
    const float* ew  = (const float*)d_in[1];
    const float* W0  = (const float*)d_in[2];
    const float* b0  = (const float*)d_in[3];
    const float* g0  = (const float*)d_in[4];
    const float* be0 = (const float*)d_in[5];
    const float* W1  = (const float*)d_in[6];
    const float* b1  = (const float*)d_in[7];
    const float* g1  = (const float*)d_in[8];
    const float* be1 = (const float*)d_in[9];
    const float* W2  = (const float*)d_in[10];
    const float* b2  = (const float*)d_in[11];
    const int*   row = (const int*)d_in[12];
    const int*   col = (const int*)d_in[13];
    float* out = (float*)d_out;

    int nrows  = in_sizes[0] / D;
    int nedges = in_sizes[1];
    float inv_n = 1.0f / (float)nrows;

    float  *hA, *hB, *stats;
    float2 *edges;
    int    *cnt;
    __nv_bfloat16 *wth, *wtl;
    cudaGetSymbolAddress((void**)&hA, g_hA);
    cudaGetSymbolAddress((void**)&hB, g_hB);
    cudaGetSymbolAddress((void**)&edges, g_edges);
    cudaGetSymbolAddress((void**)&cnt, g_cnt);
    cudaGetSymbolAddress((void**)&stats, g_stats);
    cudaGetSymbolAddress((void**)&wth, g_wt_hi);
    cudaGetSymbolAddress((void**)&wtl, g_wt_lo);

    const int SMEM_BYTES = 1024 + 2 * 128 * BSTRIDE * 2 + 2 * 128 * ASTRIDE * 2;
    cudaFuncSetAttribute(gemm_mma_kernel,
                         cudaFuncAttributeMaxDynamicSharedMemorySize, SMEM_BYTES);

    dim3 gemm_grid((nrows + 127) / 128);
    int  spmm_grid = 2048;

    prep_kernel<<<512, 256>>>(W0, W1, W2, wth, wtl, cnt, stats, nrows);
    scatter_kernel<<<(nedges + 255) / 256, 256>>>(row, col, ew, edges, cnt, nedges);

    // ---- layer 1 ----
    gemm_mma_kernel<<<gemm_grid, 256, SMEM_BYTES>>>(
        x, wth + 0 * D * D, wtl + 0 * D * D, b0,
        nullptr, nullptr, nullptr, inv_n, hA, nrows, 0);
    spmm_kernel<<<spmm_grid, 256>>>(cnt, edges, hA, hB, stats, nrows, 1);

    // ---- layer 2 (BN finalize + BN+ReLU fused into GEMM) ----
    gemm_mma_kernel<<<gemm_grid, 256, SMEM_BYTES>>>(
        hB, wth + 1 * D * D, wtl + 1 * D * D, b1,
        stats, g0, be0, inv_n, hA, nrows, 1);
    spmm_kernel<<<spmm_grid, 256>>>(cnt, edges, hA, hB, stats + 2 * D, nrows, 1);

    // ---- layer 3 ----
    gemm_mma_kernel<<<gemm_grid, 256, SMEM_BYTES>>>(
        hB, wth + 2 * D * D, wtl + 2 * D * D, b2,
        stats + 2 * D, g1, be1, inv_n, hA, nrows, 1);
    spmm_kernel<<<spmm_grid, 256>>>(cnt, edges, hA, out, nullptr, nrows, 0);
}

// round 10
// speedup vs baseline: 1.1483x; 1.1483x over previous
#include <cuda_runtime.h>
#include <cuda_bf16.h>
#include <cstdint>
#include <cstddef>

#define D 128
#define EPS_BN 1e-5f
#define MAX_NODES 100000
#define CAP 96
#define BSTRIDE 136      // B smem row stride in bf16 (68 words: conflict-free)
#define ASTRIDE 72       // A smem row stride in bf16 (36 words: conflict-free)

// ---------------- scratch (__device__ globals; allocation-free rule) --------
__device__ float  g_hA[(size_t)MAX_NODES * D];
__device__ float  g_hB[(size_t)MAX_NODES * D];
__device__ float2 g_edges[(size_t)MAX_NODES * CAP];
__device__ int    g_cnt[MAX_NODES];
__device__ float  g_stats[4 * D];
__device__ __nv_bfloat16 g_wt_hi[3][D * D];   // W^T split-hi, [n][k]
__device__ __nv_bfloat16 g_wt_lo[3][D * D];   // W^T split-lo, [n][k]

// ---------------- f32x2 helpers ---------------------------------------------
__device__ __forceinline__ unsigned long long pack2s(float v) {
    unsigned long long r;
    asm("mov.b64 %0, {%1, %1};" : "=l"(r) : "f"(v));
    return r;
}
__device__ __forceinline__ void unpack2(unsigned long long v, float& lo, float& hi) {
    asm("mov.b64 {%0, %1}, %2;" : "=f"(lo), "=f"(hi) : "l"(v));
}
__device__ __forceinline__ unsigned long long ffma2(
    unsigned long long a, unsigned long long b, unsigned long long c) {
    unsigned long long d;
    asm("fma.rn.f32x2 %0, %1, %2, %3;" : "=l"(d) : "l"(a), "l"(b), "l"(c));
    return d;
}

// ---------------- prep: zero cnt/stats + W transpose/split (one launch) -----
__global__ void prep_kernel(const float* __restrict__ W0, const float* __restrict__ W1,
                            const float* __restrict__ W2,
                            __nv_bfloat16* __restrict__ th, __nv_bfloat16* __restrict__ tl,
                            int* __restrict__ cnt, float* __restrict__ stats, int n) {
    int i = blockIdx.x * blockDim.x + threadIdx.x;
    int stride = gridDim.x * blockDim.x;
    for (int j = i; j < n; j += stride) cnt[j] = 0;
    if (i < 4 * D) stats[i] = 0.0f;
    for (int j = i; j < 3 * D * D; j += stride) {
        int layer = j >> 14;
        int idx   = j & (D * D - 1);
        const float* W = (layer == 0) ? W0 : (layer == 1) ? W1 : W2;
        int nn = idx & 127, k = idx >> 7;
        float v = W[idx];
        __nv_bfloat16 h = __float2bfloat16(v);
        float r = v - __bfloat162float(h);
        th[layer * D * D + nn * D + k] = h;
        tl[layer * D * D + nn * D + k] = __float2bfloat16(r);
    }
}

// ---------------- scatter edges into per-row buckets ------------------------
__global__ void scatter_kernel(const int* __restrict__ row, const int* __restrict__ col,
                               const float* __restrict__ w, float2* __restrict__ edges,
                               int* __restrict__ cnt, int nedges) {
    int e = blockIdx.x * blockDim.x + threadIdx.x;
    if (e >= nedges) return;
    int r = row[e];
    int slot = atomicAdd(&cnt[r], 1);
    if (slot < CAP)
        edges[(size_t)r * CAP + slot] = make_float2(__int_as_float(col[e]), w[e]);
}

// ---------------- warp-tile MMA ----------------------------------------------
__device__ __forceinline__ void mma16816(float* c, const uint32_t* a, const uint32_t* b) {
    asm volatile(
        "mma.sync.aligned.m16n8k16.row.col.f32.bf16.bf16.f32 "
        "{%0,%1,%2,%3}, {%4,%5,%6,%7}, {%8,%9}, {%0,%1,%2,%3};"
        : "+f"(c[0]), "+f"(c[1]), "+f"(c[2]), "+f"(c[3])
        : "r"(a[0]), "r"(a[1]), "r"(a[2]), "r"(a[3]), "r"(b[0]), "r"(b[1]));
}

// truncation split of 2 floats -> (hi bf16x2, lo bf16x2)
__device__ __forceinline__ void split2(float vx, float vy, uint32_t& hi2, uint32_t& lo2) {
    uint32_t bx = __float_as_uint(vx) & 0xffff0000u;
    uint32_t by = __float_as_uint(vy) & 0xffff0000u;
    hi2 = __byte_perm(bx, by, 0x7632);
    float lx = vx - __uint_as_float(bx);
    float ly = vy - __uint_as_float(by);
    __nv_bfloat162 l = __floats2bfloat162_rn(lx, ly);
    lo2 = *(uint32_t*)&l;
}

// GEMM: Y = act(X) @ W + b; act = relu(bn) from raw column stats in-kernel.
__global__ __launch_bounds__(256, 2) void gemm_mma_kernel(
    const float* __restrict__ X,
    const __nv_bfloat16* __restrict__ Wt_hi, const __nv_bfloat16* __restrict__ Wt_lo,
    const float* __restrict__ bias,
    const float* __restrict__ stats,
    const float* __restrict__ gamma, const float* __restrict__ beta,
    float inv_n,
    float* __restrict__ Y, int nrows, int use_bn)
{
    extern __shared__ __align__(16) char dsm[];
    float* s_scale = (float*)dsm;
    float* s_shift = s_scale + D;
    __nv_bfloat16* Bh = (__nv_bfloat16*)(dsm + 1024);
    __nv_bfloat16* Bl = Bh + 128 * BSTRIDE;
    __nv_bfloat16* Ah = Bl + 128 * BSTRIDE;
    __nv_bfloat16* Al = Ah + 128 * ASTRIDE;

    int t = threadIdx.x, lane = t & 31, wid = t >> 5;
    int row0 = blockIdx.x * 128;
    int g = lane >> 2, tg = lane & 3;

    if (use_bn && t < D) {
        float m   = stats[t] * inv_n;
        float var = stats[D + t] * inv_n - m * m;
        float rs  = rsqrtf(var + EPS_BN);
        float sc  = gamma[t] * rs;
        s_scale[t] = sc;
        s_shift[t] = beta[t] - m * sc;
    }

    for (int i = t; i < 2048; i += 256) {
        int n  = i >> 4;
        int c8 = i & 15;
        *(uint4*)&Bh[n * BSTRIDE + c8 * 8] = *(const uint4*)&Wt_hi[n * D + c8 * 8];
        *(uint4*)&Bl[n * BSTRIDE + c8 * 8] = *(const uint4*)&Wt_lo[n * D + c8 * 8];
    }

    int m0 = (wid & 1) * 64;
    int n0 = (wid >> 1) * 32;

    float acc[4][4][4];
#pragma unroll
    for (int mt = 0; mt < 4; mt++)
#pragma unroll
        for (int nt = 0; nt < 4; nt++)
#pragma unroll
            for (int j = 0; j < 4; j++) acc[mt][nt][j] = 0.0f;

    __syncthreads();

#pragma unroll
    for (int kh = 0; kh < 2; kh++) {
        for (int i = t; i < 2048; i += 256) {
            int r  = i >> 4;
            int f4 = i & 15;
            int col0 = kh * 64 + f4 * 4;
            int row = row0 + r;
            float4 v = make_float4(0.f, 0.f, 0.f, 0.f);
            if (row < nrows) {
                v = *(const float4*)&X[(size_t)row * D + col0];
                if (use_bn) {
                    v.x = fmaxf(fmaf(v.x, s_scale[col0 + 0], s_shift[col0 + 0]), 0.0f);
                    v.y = fmaxf(fmaf(v.y, s_scale[col0 + 1], s_shift[col0 + 1]), 0.0f);
                    v.z = fmaxf(fmaf(v.z, s_scale[col0 + 2], s_shift[col0 + 2]), 0.0f);
                    v.w = fmaxf(fmaf(v.w, s_scale[col0 + 3], s_shift[col0 + 3]), 0.0f);
                }
            }
            uint2 ph, pl;
            split2(v.x, v.y, ph.x, pl.x);
            split2(v.z, v.w, ph.y, pl.y);
            *(uint2*)&Ah[r * ASTRIDE + f4 * 4] = ph;
            *(uint2*)&Al[r * ASTRIDE + f4 * 4] = pl;
        }
        __syncthreads();

#pragma unroll
        for (int pass = 0; pass < 3; pass++) {
            const __nv_bfloat16* Asm = (pass < 2) ? Ah : Al;
            const __nv_bfloat16* Bsm = (pass == 1) ? Bl : Bh;
#pragma unroll
            for (int ks = 0; ks < 4; ks++) {
                uint32_t a[4][4];
#pragma unroll
                for (int mt = 0; mt < 4; mt++) {
                    const uint32_t* p0 =
                        (const uint32_t*)&Asm[(m0 + mt * 16 + g) * ASTRIDE] + ks * 8 + tg;
                    const uint32_t* p1 =
                        (const uint32_t*)&Asm[(m0 + mt * 16 + g + 8) * ASTRIDE] + ks * 8 + tg;
                    a[mt][0] = p0[0];
                    a[mt][1] = p1[0];
                    a[mt][2] = p0[4];
                    a[mt][3] = p1[4];
                }
                uint32_t b[4][2];
#pragma unroll
                for (int nt = 0; nt < 4; nt++) {
                    const uint32_t* pb =
                        (const uint32_t*)&Bsm[(n0 + nt * 8 + g) * BSTRIDE]
                        + kh * 32 + ks * 8 + tg;
                    b[nt][0] = pb[0];
                    b[nt][1] = pb[4];
                }
#pragma unroll
                for (int mt = 0; mt < 4; mt++)
#pragma unroll
                    for (int nt = 0; nt < 4; nt++)
                        mma16816(acc[mt][nt], a[mt], b[nt]);
            }
        }
        __syncthreads();
    }

    float2 bv[4];
#pragma unroll
    for (int nt = 0; nt < 4; nt++) {
        int cidx = n0 + nt * 8 + tg * 2;
        bv[nt] = *(const float2*)&bias[cidx];
    }
#pragma unroll
    for (int mt = 0; mt < 4; mt++) {
        int ra = row0 + m0 + mt * 16 + g;
        int rb = ra + 8;
#pragma unroll
        for (int nt = 0; nt < 4; nt++) {
            int cidx = n0 + nt * 8 + tg * 2;
            if (ra < nrows) {
                float2 o = make_float2(acc[mt][nt][0] + bv[nt].x,
                                       acc[mt][nt][1] + bv[nt].y);
                *(float2*)&Y[(size_t)ra * D + cidx] = o;
            }
            if (rb < nrows) {
                float2 o = make_float2(acc[mt][nt][2] + bv[nt].x,
                                       acc[mt][nt][3] + bv[nt].y);
                *(float2*)&Y[(size_t)rb * D + cidx] = o;
            }
        }
    }
}

// ---------------- SpMM: warp/row, coalesced edge batch + shfl, 8-deep MLP ---
__global__ __launch_bounds__(256) void spmm_kernel(
    const int* __restrict__ cnt, const float2* __restrict__ edges,
    const float* __restrict__ H, float* __restrict__ out,
    float* __restrict__ stats, int nrows, int with_stats)
{
    __shared__ float s_st[2 * D];

    int lane  = threadIdx.x & 31;
    int warp  = blockIdx.x * 8 + (threadIdx.x >> 5);
    int nwarp = gridDim.x * 8;

    if (with_stats) {
        for (int i = threadIdx.x; i < 2 * D; i += 256) s_st[i] = 0.0f;
        __syncthreads();
    }

    float4 ssum = make_float4(0.f, 0.f, 0.f, 0.f);
    float4 ssq  = make_float4(0.f, 0.f, 0.f, 0.f);

    for (int r = warp; r < nrows; r += nwarp) {
        int deg = __ldg(&cnt[r]);
        const float2* bucket = &edges[(size_t)r * CAP];
        unsigned long long a01 = 0ULL, a23 = 0ULL;

        for (int base = 0; base < deg; base += 32) {
            // one coalesced batch load of up to 32 edge records
            float2 e = make_float2(0.0f, 0.0f);   // pad: col 0 (valid), weight 0
            if (base + lane < deg) e = bucket[base + lane];
            int   ci = __float_as_int(e.x);
            float wi = e.y;
            int   m  = min(32, deg - base);

            for (int b2 = 0; b2 < m; b2 += 8) {
                int   cc[8];
                float ww[8];
#pragma unroll
                for (int jj = 0; jj < 8; jj++) {
                    cc[jj] = __shfl_sync(0xffffffffu, ci, b2 + jj);
                    ww[jj] = __shfl_sync(0xffffffffu, wi, b2 + jj);
                }
                // 8 independent 16B gathers (MLP=8), then packed FMAs
                ulonglong2 v[8];
#pragma unroll
                for (int jj = 0; jj < 8; jj++)
                    v[jj] = *(const ulonglong2*)&H[(size_t)cc[jj] * D + lane * 4];
#pragma unroll
                for (int jj = 0; jj < 8; jj++) {
                    unsigned long long w2 = pack2s(ww[jj]);
                    a01 = ffma2(v[jj].x, w2, a01);
                    a23 = ffma2(v[jj].y, w2, a23);
                }
            }
        }

        float4 acc;
        unpack2(a01, acc.x, acc.y);
        unpack2(a23, acc.z, acc.w);
        *(float4*)&out[(size_t)r * D + lane * 4] = acc;

        if (with_stats) {
            ssum.x += acc.x; ssum.y += acc.y; ssum.z += acc.z; ssum.w += acc.w;
            ssq.x += acc.x * acc.x; ssq.y += acc.y * acc.y;
            ssq.z += acc.z * acc.z; ssq.w += acc.w * acc.w;
        }
    }

    if (with_stats) {
        atomicAdd(&s_st[lane * 4 + 0], ssum.x);
        atomicAdd(&s_st[lane * 4 + 1], ssum.y);
        atomicAdd(&s_st[lane * 4 + 2], ssum.z);
        atomicAdd(&s_st[lane * 4 + 3], ssum.w);
        atomicAdd(&s_st[D + lane * 4 + 0], ssq.x);
        atomicAdd(&s_st[D + lane * 4 + 1], ssq.y);
        atomicAdd(&s_st[D + lane * 4 + 2], ssq.z);
        atomicAdd(&s_st[D + lane * 4 + 3], ssq.w);
        __syncthreads();
        for (int i = threadIdx.x; i < 2 * D; i += 256)
            atomicAdd(&stats[i], s_st[i]);
    }
}

// ---------------- launch -----------------------------------------------------
extern "C" void kernel_launch(void* const* d_in, const int* in_sizes, int n_in,
                              void* d_out, int out_size)
{
    const float* x   = (const float*)d_in[0];
    const float* ew  = (const float*)d_in[1];
    const float* W0  = (const float*)d_in[2];
    const float* b0  = (const float*)d_in[3];
    const float* g0  = (const float*)d_in[4];
    const float* be0 = (const float*)d_in[5];
    const float* W1  = (const float*)d_in[6];
    const float* b1  = (const float*)d_in[7];
    const float* g1  = (const float*)d_in[8];
    const float* be1 = (const float*)d_in[9];
    const float* W2  = (const float*)d_in[10];
    const float* b2  = (const float*)d_in[11];
    const int*   row = (const int*)d_in[12];
    const int*   col = (const int*)d_in[13];
    float* out = (float*)d_out;

    int nrows  = in_sizes[0] / D;
    int nedges = in_sizes[1];
    float inv_n = 1.0f / (float)nrows;

    float  *hA, *hB, *stats;
    float2 *edges;
    int    *cnt;
    __nv_bfloat16 *wth, *wtl;
    cudaGetSymbolAddress((void**)&hA, g_hA);
    cudaGetSymbolAddress((void**)&hB, g_hB);
    cudaGetSymbolAddress((void**)&edges, g_edges);
    cudaGetSymbolAddress((void**)&cnt, g_cnt);
    cudaGetSymbolAddress((void**)&stats, g_stats);
    cudaGetSymbolAddress((void**)&wth, g_wt_hi);
    cudaGetSymbolAddress((void**)&wtl, g_wt_lo);

    const int SMEM_BYTES = 1024 + 2 * 128 * BSTRIDE * 2 + 2 * 128 * ASTRIDE * 2;
    cudaFuncSetAttribute(gemm_mma_kernel,
                         cudaFuncAttributeMaxDynamicSharedMemorySize, SMEM_BYTES);

    dim3 gemm_grid((nrows + 127) / 128);
    int  spmm_grid = 2048;

    prep_kernel<<<512, 256>>>(W0, W1, W2, wth, wtl, cnt, stats, nrows);
    scatter_kernel<<<(nedges + 255) / 256, 256>>>(row, col, ew, edges, cnt, nedges);

    // ---- layer 1 ----
    gemm_mma_kernel<<<gemm_grid, 256, SMEM_BYTES>>>(
        x, wth + 0 * D * D, wtl + 0 * D * D, b0,
        nullptr, nullptr, nullptr, inv_n, hA, nrows, 0);
    spmm_kernel<<<spmm_grid, 256>>>(cnt, edges, hA, hB, stats, nrows, 1);

    // ---- layer 2 (BN finalize + BN+ReLU fused into GEMM) ----
    gemm_mma_kernel<<<gemm_grid, 256, SMEM_BYTES>>>(
        hB, wth + 1 * D * D, wtl + 1 * D * D, b1,
        stats, g0, be0, inv_n, hA, nrows, 1);
    spmm_kernel<<<spmm_grid, 256>>>(cnt, edges, hA, hB, stats + 2 * D, nrows, 1);

    // ---- layer 3 ----
    gemm_mma_kernel<<<gemm_grid, 256, SMEM_BYTES>>>(
        hB, wth + 2 * D * D, wtl + 2 * D * D, b2,
        stats + 2 * D, g1, be1, inv_n, hA, nrows, 1);
    spmm_kernel<<<spmm_grid, 256>>>(cnt, edges, hA, out, nullptr, nrows, 0);
}

// round 12
// speedup vs baseline: 1.1955x; 1.0411x over previous
#include <cuda_runtime.h>
#include <cuda_bf16.h>
#include <cuda_fp16.h>
#include <cstdint>
#include <cstddef>

#define D 128
#define EPS_BN 1e-5f
#define MAX_NODES 100000
#define CAP 96
#define BSTRIDE 136      // B smem row stride in bf16 (68 words: conflict-free)
#define ASTRIDE 72       // A smem row stride in bf16 (36 words: conflict-free)

// ---------------- scratch (__device__ globals; allocation-free rule) --------
__device__ __half g_hY[(size_t)MAX_NODES * D];     // GEMM output (fp16), SpMM gather src
__device__ float  g_hB[(size_t)MAX_NODES * D];     // SpMM output (fp32), GEMM input
__device__ float2 g_edges[(size_t)MAX_NODES * CAP];
__device__ int    g_cnt[MAX_NODES];
__device__ float  g_stats[4 * D];
__device__ __nv_bfloat16 g_wt_hi[3][D * D];   // W^T split-hi, [n][k]
__device__ __nv_bfloat16 g_wt_lo[3][D * D];   // W^T split-lo, [n][k]

// ---------------- prep: zero cnt/stats + W transpose/split (one launch) -----
__global__ void prep_kernel(const float* __restrict__ W0, const float* __restrict__ W1,
                            const float* __restrict__ W2,
                            __nv_bfloat16* __restrict__ th, __nv_bfloat16* __restrict__ tl,
                            int* __restrict__ cnt, float* __restrict__ stats, int n) {
    int i = blockIdx.x * blockDim.x + threadIdx.x;
    int stride = gridDim.x * blockDim.x;
    for (int j = i; j < n; j += stride) cnt[j] = 0;
    if (i < 4 * D) stats[i] = 0.0f;
    for (int j = i; j < 3 * D * D; j += stride) {
        int layer = j >> 14;
        int idx   = j & (D * D - 1);
        const float* W = (layer == 0) ? W0 : (layer == 1) ? W1 : W2;
        int nn = idx & 127, k = idx >> 7;
        float v = W[idx];
        __nv_bfloat16 h = __float2bfloat16(v);
        float r = v - __bfloat162float(h);
        th[layer * D * D + nn * D + k] = h;
        tl[layer * D * D + nn * D + k] = __float2bfloat16(r);
    }
}

// ---------------- scatter edges into per-row buckets ------------------------
__global__ void scatter_kernel(const int* __restrict__ row, const int* __restrict__ col,
                               const float* __restrict__ w, float2* __restrict__ edges,
                               int* __restrict__ cnt, int nedges) {
    int e = blockIdx.x * blockDim.x + threadIdx.x;
    if (e >= nedges) return;
    int r = row[e];
    int slot = atomicAdd(&cnt[r], 1);
    if (slot < CAP)
        edges[(size_t)r * CAP + slot] = make_float2(__int_as_float(col[e]), w[e]);
}

// ---------------- warp-tile MMA ----------------------------------------------
__device__ __forceinline__ void mma16816(float* c, const uint32_t* a, const uint32_t* b) {
    asm volatile(
        "mma.sync.aligned.m16n8k16.row.col.f32.bf16.bf16.f32 "
        "{%0,%1,%2,%3}, {%4,%5,%6,%7}, {%8,%9}, {%0,%1,%2,%3};"
        : "+f"(c[0]), "+f"(c[1]), "+f"(c[2]), "+f"(c[3])
        : "r"(a[0]), "r"(a[1]), "r"(a[2]), "r"(a[3]), "r"(b[0]), "r"(b[1]));
}

// truncation split of 2 floats -> (hi bf16x2, lo bf16x2)
__device__ __forceinline__ void split2(float vx, float vy, uint32_t& hi2, uint32_t& lo2) {
    uint32_t bx = __float_as_uint(vx) & 0xffff0000u;
    uint32_t by = __float_as_uint(vy) & 0xffff0000u;
    hi2 = __byte_perm(bx, by, 0x7632);
    float lx = vx - __uint_as_float(bx);
    float ly = vy - __uint_as_float(by);
    __nv_bfloat162 l = __floats2bfloat162_rn(lx, ly);
    lo2 = *(uint32_t*)&l;
}

// GEMM: Y(fp16) = act(X) @ W + b; act = relu(bn) from raw column stats.
__global__ __launch_bounds__(256, 2) void gemm_mma_kernel(
    const float* __restrict__ X,
    const __nv_bfloat16* __restrict__ Wt_hi, const __nv_bfloat16* __restrict__ Wt_lo,
    const float* __restrict__ bias,
    const float* __restrict__ stats,
    const float* __restrict__ gamma, const float* __restrict__ beta,
    float inv_n,
    __half* __restrict__ Y, int nrows, int use_bn)
{
    extern __shared__ __align__(16) char dsm[];
    float* s_scale = (float*)dsm;
    float* s_shift = s_scale + D;
    __nv_bfloat16* Bh = (__nv_bfloat16*)(dsm + 1024);
    __nv_bfloat16* Bl = Bh + 128 * BSTRIDE;
    __nv_bfloat16* Ah = Bl + 128 * BSTRIDE;
    __nv_bfloat16* Al = Ah + 128 * ASTRIDE;

    int t = threadIdx.x, lane = t & 31, wid = t >> 5;
    int row0 = blockIdx.x * 128;
    int g = lane >> 2, tg = lane & 3;

    if (use_bn && t < D) {
        float m   = stats[t] * inv_n;
        float var = stats[D + t] * inv_n - m * m;
        float rs  = rsqrtf(var + EPS_BN);
        float sc  = gamma[t] * rs;
        s_scale[t] = sc;
        s_shift[t] = beta[t] - m * sc;
    }

    for (int i = t; i < 2048; i += 256) {
        int n  = i >> 4;
        int c8 = i & 15;
        *(uint4*)&Bh[n * BSTRIDE + c8 * 8] = *(const uint4*)&Wt_hi[n * D + c8 * 8];
        *(uint4*)&Bl[n * BSTRIDE + c8 * 8] = *(const uint4*)&Wt_lo[n * D + c8 * 8];
    }

    int m0 = (wid & 1) * 64;
    int n0 = (wid >> 1) * 32;

    float acc[4][4][4];
#pragma unroll
    for (int mt = 0; mt < 4; mt++)
#pragma unroll
        for (int nt = 0; nt < 4; nt++)
#pragma unroll
            for (int j = 0; j < 4; j++) acc[mt][nt][j] = 0.0f;

    __syncthreads();

#pragma unroll
    for (int kh = 0; kh < 2; kh++) {
        for (int i = t; i < 2048; i += 256) {
            int r  = i >> 4;
            int f4 = i & 15;
            int col0 = kh * 64 + f4 * 4;
            int row = row0 + r;
            float4 v = make_float4(0.f, 0.f, 0.f, 0.f);
            if (row < nrows) {
                v = *(const float4*)&X[(size_t)row * D + col0];
                if (use_bn) {
                    v.x = fmaxf(fmaf(v.x, s_scale[col0 + 0], s_shift[col0 + 0]), 0.0f);
                    v.y = fmaxf(fmaf(v.y, s_scale[col0 + 1], s_shift[col0 + 1]), 0.0f);
                    v.z = fmaxf(fmaf(v.z, s_scale[col0 + 2], s_shift[col0 + 2]), 0.0f);
                    v.w = fmaxf(fmaf(v.w, s_scale[col0 + 3], s_shift[col0 + 3]), 0.0f);
                }
            }
            uint2 ph, pl;
            split2(v.x, v.y, ph.x, pl.x);
            split2(v.z, v.w, ph.y, pl.y);
            *(uint2*)&Ah[r * ASTRIDE + f4 * 4] = ph;
            *(uint2*)&Al[r * ASTRIDE + f4 * 4] = pl;
        }
        __syncthreads();

#pragma unroll
        for (int pass = 0; pass < 3; pass++) {
            const __nv_bfloat16* Asm = (pass < 2) ? Ah : Al;
            const __nv_bfloat16* Bsm = (pass == 1) ? Bl : Bh;
#pragma unroll
            for (int ks = 0; ks < 4; ks++) {
                uint32_t a[4][4];
#pragma unroll
                for (int mt = 0; mt < 4; mt++) {
                    const uint32_t* p0 =
                        (const uint32_t*)&Asm[(m0 + mt * 16 + g) * ASTRIDE] + ks * 8 + tg;
                    const uint32_t* p1 =
                        (const uint32_t*)&Asm[(m0 + mt * 16 + g + 8) * ASTRIDE] + ks * 8 + tg;
                    a[mt][0] = p0[0];
                    a[mt][1] = p1[0];
                    a[mt][2] = p0[4];
                    a[mt][3] = p1[4];
                }
                uint32_t b[4][2];
#pragma unroll
                for (int nt = 0; nt < 4; nt++) {
                    const uint32_t* pb =
                        (const uint32_t*)&Bsm[(n0 + nt * 8 + g) * BSTRIDE]
                        + kh * 32 + ks * 8 + tg;
                    b[nt][0] = pb[0];
                    b[nt][1] = pb[4];
                }
#pragma unroll
                for (int mt = 0; mt < 4; mt++)
#pragma unroll
                    for (int nt = 0; nt < 4; nt++)
                        mma16816(acc[mt][nt], a[mt], b[nt]);
            }
        }
        __syncthreads();
    }

    float2 bv[4];
#pragma unroll
    for (int nt = 0; nt < 4; nt++) {
        int cidx = n0 + nt * 8 + tg * 2;
        bv[nt] = *(const float2*)&bias[cidx];
    }
#pragma unroll
    for (int mt = 0; mt < 4; mt++) {
        int ra = row0 + m0 + mt * 16 + g;
        int rb = ra + 8;
#pragma unroll
        for (int nt = 0; nt < 4; nt++) {
            int cidx = n0 + nt * 8 + tg * 2;
            if (ra < nrows) {
                __half2 o = __floats2half2_rn(acc[mt][nt][0] + bv[nt].x,
                                              acc[mt][nt][1] + bv[nt].y);
                *(__half2*)&Y[(size_t)ra * D + cidx] = o;
            }
            if (rb < nrows) {
                __half2 o = __floats2half2_rn(acc[mt][nt][2] + bv[nt].x,
                                              acc[mt][nt][3] + bv[nt].y);
                *(__half2*)&Y[(size_t)rb * D + cidx] = o;
            }
        }
    }
}

// ---------------- SpMM: warp/row, coalesced batch + shfl, fp16 gather -------
__global__ __launch_bounds__(256) void spmm_kernel(
    const int* __restrict__ cnt, const float2* __restrict__ edges,
    const __half* __restrict__ H, float* __restrict__ out,
    float* __restrict__ stats, int nrows, int with_stats)
{
    __shared__ float s_st[2 * D];

    int lane  = threadIdx.x & 31;
    int warp  = blockIdx.x * 8 + (threadIdx.x >> 5);
    int nwarp = gridDim.x * 8;

    if (with_stats) {
        for (int i = threadIdx.x; i < 2 * D; i += 256) s_st[i] = 0.0f;
        __syncthreads();
    }

    float4 ssum = make_float4(0.f, 0.f, 0.f, 0.f);
    float4 ssq  = make_float4(0.f, 0.f, 0.f, 0.f);

    for (int r = warp; r < nrows; r += nwarp) {
        int deg = __ldg(&cnt[r]);
        const float2* bucket = &edges[(size_t)r * CAP];
        float4 acc = make_float4(0.f, 0.f, 0.f, 0.f);

        for (int base = 0; base < deg; base += 32) {
            // one coalesced batch load of up to 32 edge records
            float2 e = make_float2(0.0f, 0.0f);   // pad: col 0 (valid), weight 0
            if (base + lane < deg) e = bucket[base + lane];
            int   ci = __float_as_int(e.x);
            float wi = e.y;
            int   m  = min(32, deg - base);

            for (int b2 = 0; b2 < m; b2 += 8) {
                int   cc[8];
                float ww[8];
#pragma unroll
                for (int jj = 0; jj < 8; jj++) {
                    cc[jj] = __shfl_sync(0xffffffffu, ci, b2 + jj);
                    ww[jj] = __shfl_sync(0xffffffffu, wi, b2 + jj);
                }
                // 8 independent 8B fp16 gathers (MLP=8)
                uint2 v[8];
#pragma unroll
                for (int jj = 0; jj < 8; jj++)
                    v[jj] = *(const uint2*)&H[(size_t)cc[jj] * D + lane * 4];
#pragma unroll
                for (int jj = 0; jj < 8; jj++) {
                    float2 f01 = __half22float2(*(__half2*)&v[jj].x);
                    float2 f23 = __half22float2(*(__half2*)&v[jj].y);
                    acc.x += ww[jj] * f01.x;
                    acc.y += ww[jj] * f01.y;
                    acc.z += ww[jj] * f23.x;
                    acc.w += ww[jj] * f23.y;
                }
            }
        }

        // evict-first store: keep H + edges resident in L2 during the gather
        {
            float* dst = &out[(size_t)r * D + lane * 4];
            asm volatile("st.global.cs.v4.f32 [%0], {%1,%2,%3,%4};"
                         :: "l"(dst), "f"(acc.x), "f"(acc.y), "f"(acc.z), "f"(acc.w)
                         : "memory");
        }

        if (with_stats) {
            ssum.x += acc.x; ssum.y += acc.y; ssum.z += acc.z; ssum.w += acc.w;
            ssq.x += acc.x * acc.x; ssq.y += acc.y * acc.y;
            ssq.z += acc.z * acc.z; ssq.w += acc.w * acc.w;
        }
    }

    if (with_stats) {
        atomicAdd(&s_st[lane * 4 + 0], ssum.x);
        atomicAdd(&s_st[lane * 4 + 1], ssum.y);
        atomicAdd(&s_st[lane * 4 + 2], ssum.z);
        atomicAdd(&s_st[lane * 4 + 3], ssum.w);
        atomicAdd(&s_st[D + lane * 4 + 0], ssq.x);
        atomicAdd(&s_st[D + lane * 4 + 1], ssq.y);
        atomicAdd(&s_st[D + lane * 4 + 2], ssq.z);
        atomicAdd(&s_st[D + lane * 4 + 3], ssq.w);
        __syncthreads();
        for (int i = threadIdx.x; i < 2 * D; i += 256)
            atomicAdd(&stats[i], s_st[i]);
    }
}

// ---------------- launch -----------------------------------------------------
extern "C" void kernel_launch(void* const* d_in, const int* in_sizes, int n_in,
                              void* d_out, int out_size)
{
    const float* x   = (const float*)d_in[0];
    const float* ew  = (const float*)d_in[1];
    const float* W0  = (const float*)d_in[2];
    const float* b0  = (const float*)d_in[3];
    const float* g0  = (const float*)d_in[4];
    const float* be0 = (const float*)d_in[5];
    const float* W1  = (const float*)d_in[6];
    const float* b1  = (const float*)d_in[7];
    const float* g1  = (const float*)d_in[8];
    const float* be1 = (const float*)d_in[9];
    const float* W2  = (const float*)d_in[10];
    const float* b2  = (const float*)d_in[11];
    const int*   row = (const int*)d_in[12];
    const int*   col = (const int*)d_in[13];
    float* out = (float*)d_out;

    int nrows  = in_sizes[0] / D;
    int nedges = in_sizes[1];
    float inv_n = 1.0f / (float)nrows;

    float  *hB, *stats;
    __half *hY;
    float2 *edges;
    int    *cnt;
    __nv_bfloat16 *wth, *wtl;
    cudaGetSymbolAddress((void**)&hY, g_hY);
    cudaGetSymbolAddress((void**)&hB, g_hB);
    cudaGetSymbolAddress((void**)&edges, g_edges);
    cudaGetSymbolAddress((void**)&cnt, g_cnt);
    cudaGetSymbolAddress((void**)&stats, g_stats);
    cudaGetSymbolAddress((void**)&wth, g_wt_hi);
    cudaGetSymbolAddress((void**)&wtl, g_wt_lo);

    const int SMEM_BYTES = 1024 + 2 * 128 * BSTRIDE * 2 + 2 * 128 * ASTRIDE * 2;
    cudaFuncSetAttribute(gemm_mma_kernel,
                         cudaFuncAttributeMaxDynamicSharedMemorySize, SMEM_BYTES);

    dim3 gemm_grid((nrows + 127) / 128);
    int  spmm_grid = 2048;

    prep_kernel<<<512, 256>>>(W0, W1, W2, wth, wtl, cnt, stats, nrows);
    scatter_kernel<<<(nedges + 255) / 256, 256>>>(row, col, ew, edges, cnt, nedges);

    // ---- layer 1 ----
    gemm_mma_kernel<<<gemm_grid, 256, SMEM_BYTES>>>(
        x, wth + 0 * D * D, wtl + 0 * D * D, b0,
        nullptr, nullptr, nullptr, inv_n, hY, nrows, 0);
    spmm_kernel<<<spmm_grid, 256>>>(cnt, edges, hY, hB, stats, nrows, 1);

    // ---- layer 2 (BN finalize + BN+ReLU fused into GEMM) ----
    gemm_mma_kernel<<<gemm_grid, 256, SMEM_BYTES>>>(
        hB, wth + 1 * D * D, wtl + 1 * D * D, b1,
        stats, g0, be0, inv_n, hY, nrows, 1);
    spmm_kernel<<<spmm_grid, 256>>>(cnt, edges, hY, hB, stats + 2 * D, nrows, 1);

    // ---- layer 3 ----
    gemm_mma_kernel<<<gemm_grid, 256, SMEM_BYTES>>>(
        hB, wth + 2 * D * D, wtl + 2 * D * D, b2,
        stats + 2 * D, g1, be1, inv_n, hY, nrows, 1);
    spmm_kernel<<<spmm_grid, 256>>>(cnt, edges, hY, out, nullptr, nrows, 0);
}

// round 13
// speedup vs baseline: 1.2007x; 1.0044x over previous
#include <cuda_runtime.h>
#include <cuda_bf16.h>
#include <cuda_fp16.h>
#include <cstdint>
#include <cstddef>

#define D 128
#define EPS_BN 1e-5f
#define MAX_NODES 100000
#define CAP 96
#define BSTRIDE 136      // B smem row stride in bf16 (68 words: conflict-free)
#define ASTRIDE 72       // A smem row stride in bf16 (36 words: conflict-free)

// ---------------- scratch (__device__ globals; allocation-free rule) --------
__device__ __half g_hY[(size_t)MAX_NODES * D];     // GEMM output (fp16), SpMM gather src
__device__ float  g_hB[(size_t)MAX_NODES * D];     // SpMM output (fp32), GEMM input
__device__ float2 g_edges[(size_t)MAX_NODES * CAP];
__device__ int    g_cnt[MAX_NODES];
__device__ float  g_stats[4 * D];
__device__ __nv_bfloat16 g_wt_hi[3][D * D];   // W^T split-hi, [n][k]
__device__ __nv_bfloat16 g_wt_lo[3][D * D];   // W^T split-lo, [n][k]

// ---------------- helpers -----------------------------------------------------
__device__ __forceinline__ uint32_t smem_u32(const void* p) {
    uint32_t a;
    asm("{ .reg .u64 t; cvta.to.shared.u64 t, %1; cvt.u32.u64 %0, t; }"
        : "=r"(a) : "l"(p));
    return a;
}
#define LDSM_X4(r0, r1, r2, r3, addr) \
    asm volatile("ldmatrix.sync.aligned.m8n8.x4.shared.b16 {%0,%1,%2,%3}, [%4];" \
        : "=r"(r0), "=r"(r1), "=r"(r2), "=r"(r3) : "r"(addr))

// ---------------- prep: zero cnt/stats + W transpose/split (one launch) -----
__global__ void prep_kernel(const float* __restrict__ W0, const float* __restrict__ W1,
                            const float* __restrict__ W2,
                            __nv_bfloat16* __restrict__ th, __nv_bfloat16* __restrict__ tl,
                            int* __restrict__ cnt, float* __restrict__ stats, int n) {
    int i = blockIdx.x * blockDim.x + threadIdx.x;
    int stride = gridDim.x * blockDim.x;
    for (int j = i; j < n; j += stride) cnt[j] = 0;
    if (i < 4 * D) stats[i] = 0.0f;
    for (int j = i; j < 3 * D * D; j += stride) {
        int layer = j >> 14;
        int idx   = j & (D * D - 1);
        const float* W = (layer == 0) ? W0 : (layer == 1) ? W1 : W2;
        int nn = idx & 127, k = idx >> 7;
        float v = W[idx];
        __nv_bfloat16 h = __float2bfloat16(v);
        float r = v - __bfloat162float(h);
        th[layer * D * D + nn * D + k] = h;
        tl[layer * D * D + nn * D + k] = __float2bfloat16(r);
    }
}

// ---------------- scatter edges into per-row buckets ------------------------
__global__ void scatter_kernel(const int* __restrict__ row, const int* __restrict__ col,
                               const float* __restrict__ w, float2* __restrict__ edges,
                               int* __restrict__ cnt, int nedges) {
    int e = blockIdx.x * blockDim.x + threadIdx.x;
    if (e >= nedges) return;
    int r = row[e];
    int slot = atomicAdd(&cnt[r], 1);
    if (slot < CAP)
        edges[(size_t)r * CAP + slot] = make_float2(__int_as_float(col[e]), w[e]);
}

// ---------------- warp-tile MMA ----------------------------------------------
__device__ __forceinline__ void mma16816(float* c, const uint32_t* a, const uint32_t* b) {
    asm volatile(
        "mma.sync.aligned.m16n8k16.row.col.f32.bf16.bf16.f32 "
        "{%0,%1,%2,%3}, {%4,%5,%6,%7}, {%8,%9}, {%0,%1,%2,%3};"
        : "+f"(c[0]), "+f"(c[1]), "+f"(c[2]), "+f"(c[3])
        : "r"(a[0]), "r"(a[1]), "r"(a[2]), "r"(a[3]), "r"(b[0]), "r"(b[1]));
}

// truncation split of 2 floats -> (hi bf16x2, lo bf16x2)
__device__ __forceinline__ void split2(float vx, float vy, uint32_t& hi2, uint32_t& lo2) {
    uint32_t bx = __float_as_uint(vx) & 0xffff0000u;
    uint32_t by = __float_as_uint(vy) & 0xffff0000u;
    hi2 = __byte_perm(bx, by, 0x7632);
    float lx = vx - __uint_as_float(bx);
    float ly = vy - __uint_as_float(by);
    __nv_bfloat162 l = __floats2bfloat162_rn(lx, ly);
    lo2 = *(uint32_t*)&l;
}

// GEMM: Y(fp16) = act(X) @ W + b; act = relu(bn) from raw column stats.
__global__ __launch_bounds__(256, 2) void gemm_mma_kernel(
    const float* __restrict__ X,
    const __nv_bfloat16* __restrict__ Wt_hi, const __nv_bfloat16* __restrict__ Wt_lo,
    const float* __restrict__ bias,
    const float* __restrict__ stats,
    const float* __restrict__ gamma, const float* __restrict__ beta,
    float inv_n,
    __half* __restrict__ Y, int nrows, int use_bn)
{
    extern __shared__ __align__(16) char dsm[];
    float* s_scale = (float*)dsm;
    float* s_shift = s_scale + D;
    __nv_bfloat16* Bh = (__nv_bfloat16*)(dsm + 1024);
    __nv_bfloat16* Bl = Bh + 128 * BSTRIDE;
    __nv_bfloat16* Ah = Bl + 128 * BSTRIDE;
    __nv_bfloat16* Al = Ah + 128 * ASTRIDE;

    int t = threadIdx.x, lane = t & 31, wid = t >> 5;
    int row0 = blockIdx.x * 128;
    int g = lane >> 2, tg = lane & 3;

    if (use_bn && t < D) {
        float m   = stats[t] * inv_n;
        float var = stats[D + t] * inv_n - m * m;
        float rs  = rsqrtf(var + EPS_BN);
        float sc  = gamma[t] * rs;
        s_scale[t] = sc;
        s_shift[t] = beta[t] - m * sc;
    }

    for (int i = t; i < 2048; i += 256) {
        int n  = i >> 4;
        int c8 = i & 15;
        *(uint4*)&Bh[n * BSTRIDE + c8 * 8] = *(const uint4*)&Wt_hi[n * D + c8 * 8];
        *(uint4*)&Bl[n * BSTRIDE + c8 * 8] = *(const uint4*)&Wt_lo[n * D + c8 * 8];
    }

    int m0 = (wid & 1) * 64;
    int n0 = (wid >> 1) * 32;

    // ldmatrix per-lane address components
    int a_row_local = ((lane >> 3) & 1) * 8 + (lane & 7);   // tile row within 16
    int a_colh      = (lane >> 4) * 8;                      // 0 / 8 elements (k)
    int b_row_local = ((lane >> 4) & 1) * 8 + (lane & 7);
    int b_colh      = ((lane >> 3) & 1) * 8;

    uint32_t aoffs[4], boffs[2];
#pragma unroll
    for (int mt = 0; mt < 4; mt++)
        aoffs[mt] = (uint32_t)(((m0 + mt * 16 + a_row_local) * ASTRIDE + a_colh) * 2);
#pragma unroll
    for (int ntp = 0; ntp < 2; ntp++)
        boffs[ntp] = (uint32_t)(((n0 + ntp * 16 + b_row_local) * BSTRIDE + b_colh) * 2);

    uint32_t ah_b = smem_u32(Ah), al_b = smem_u32(Al);
    uint32_t bh_b = smem_u32(Bh), bl_b = smem_u32(Bl);

    float acc[4][4][4];
#pragma unroll
    for (int mt = 0; mt < 4; mt++)
#pragma unroll
        for (int nt = 0; nt < 4; nt++)
#pragma unroll
            for (int j = 0; j < 4; j++) acc[mt][nt][j] = 0.0f;

    __syncthreads();

#pragma unroll
    for (int kh = 0; kh < 2; kh++) {
        // ---- fill A K-half: truncation split, BN+ReLU fused ----
        for (int i = t; i < 2048; i += 256) {
            int r  = i >> 4;
            int f4 = i & 15;
            int col0 = kh * 64 + f4 * 4;
            int row = row0 + r;
            float4 v = make_float4(0.f, 0.f, 0.f, 0.f);
            if (row < nrows) {
                v = *(const float4*)&X[(size_t)row * D + col0];
                if (use_bn) {
                    v.x = fmaxf(fmaf(v.x, s_scale[col0 + 0], s_shift[col0 + 0]), 0.0f);
                    v.y = fmaxf(fmaf(v.y, s_scale[col0 + 1], s_shift[col0 + 1]), 0.0f);
                    v.z = fmaxf(fmaf(v.z, s_scale[col0 + 2], s_shift[col0 + 2]), 0.0f);
                    v.w = fmaxf(fmaf(v.w, s_scale[col0 + 3], s_shift[col0 + 3]), 0.0f);
                }
            }
            uint2 ph, pl;
            split2(v.x, v.y, ph.x, pl.x);
            split2(v.z, v.w, ph.y, pl.y);
            *(uint2*)&Ah[r * ASTRIDE + f4 * 4] = ph;
            *(uint2*)&Al[r * ASTRIDE + f4 * 4] = pl;
        }
        __syncthreads();

#pragma unroll
        for (int pass = 0; pass < 3; pass++) {
            uint32_t abase = (pass < 2) ? ah_b : al_b;
            uint32_t bbase = ((pass == 1) ? bl_b : bh_b) + (uint32_t)(kh * 64 * 2);
#pragma unroll
            for (int ks = 0; ks < 4; ks++) {
                uint32_t kso = (uint32_t)(ks * 32);   // 16 bf16 = 32 bytes
                uint32_t a[4][4];
#pragma unroll
                for (int mt = 0; mt < 4; mt++)
                    LDSM_X4(a[mt][0], a[mt][1], a[mt][2], a[mt][3],
                            abase + aoffs[mt] + kso);
                uint32_t b[2][4];
#pragma unroll
                for (int ntp = 0; ntp < 2; ntp++)
                    LDSM_X4(b[ntp][0], b[ntp][1], b[ntp][2], b[ntp][3],
                            bbase + boffs[ntp] + kso);
#pragma unroll
                for (int mt = 0; mt < 4; mt++)
#pragma unroll
                    for (int nt = 0; nt < 4; nt++)
                        mma16816(acc[mt][nt], a[mt], &b[nt >> 1][(nt & 1) * 2]);
            }
        }
        __syncthreads();
    }

    float2 bv[4];
#pragma unroll
    for (int nt = 0; nt < 4; nt++) {
        int cidx = n0 + nt * 8 + tg * 2;
        bv[nt] = *(const float2*)&bias[cidx];
    }
#pragma unroll
    for (int mt = 0; mt < 4; mt++) {
        int ra = row0 + m0 + mt * 16 + g;
        int rb = ra + 8;
#pragma unroll
        for (int nt = 0; nt < 4; nt++) {
            int cidx = n0 + nt * 8 + tg * 2;
            if (ra < nrows) {
                __half2 o = __floats2half2_rn(acc[mt][nt][0] + bv[nt].x,
                                              acc[mt][nt][1] + bv[nt].y);
                *(__half2*)&Y[(size_t)ra * D + cidx] = o;
            }
            if (rb < nrows) {
                __half2 o = __floats2half2_rn(acc[mt][nt][2] + bv[nt].x,
                                              acc[mt][nt][3] + bv[nt].y);
                *(__half2*)&Y[(size_t)rb * D + cidx] = o;
            }
        }
    }
}

// ---------------- SpMM: warp/row, coalesced batch + shfl, fp16 gather -------
__global__ __launch_bounds__(256) void spmm_kernel(
    const int* __restrict__ cnt, const float2* __restrict__ edges,
    const __half* __restrict__ H, float* __restrict__ out,
    float* __restrict__ stats, int nrows, int with_stats)
{
    __shared__ float s_st[2 * D];

    int lane  = threadIdx.x & 31;
    int warp  = blockIdx.x * 8 + (threadIdx.x >> 5);
    int nwarp = gridDim.x * 8;

    if (with_stats) {
        for (int i = threadIdx.x; i < 2 * D; i += 256) s_st[i] = 0.0f;
        __syncthreads();
    }

    float4 ssum = make_float4(0.f, 0.f, 0.f, 0.f);
    float4 ssq  = make_float4(0.f, 0.f, 0.f, 0.f);

    for (int r = warp; r < nrows; r += nwarp) {
        int deg = __ldg(&cnt[r]);
        const float2* bucket = &edges[(size_t)r * CAP];
        float4 acc = make_float4(0.f, 0.f, 0.f, 0.f);

        for (int base = 0; base < deg; base += 32) {
            float2 e = make_float2(0.0f, 0.0f);
            if (base + lane < deg) e = bucket[base + lane];
            int   ci = __float_as_int(e.x);
            float wi = e.y;
            int   m  = min(32, deg - base);

            for (int b2 = 0; b2 < m; b2 += 8) {
                int   cc[8];
                float ww[8];
#pragma unroll
                for (int jj = 0; jj < 8; jj++) {
                    cc[jj] = __shfl_sync(0xffffffffu, ci, b2 + jj);
                    ww[jj] = __shfl_sync(0xffffffffu, wi, b2 + jj);
                }
                uint2 v[8];
#pragma unroll
                for (int jj = 0; jj < 8; jj++)
                    v[jj] = *(const uint2*)&H[(size_t)cc[jj] * D + lane * 4];
#pragma unroll
                for (int jj = 0; jj < 8; jj++) {
                    float2 f01 = __half22float2(*(__half2*)&v[jj].x);
                    float2 f23 = __half22float2(*(__half2*)&v[jj].y);
                    acc.x += ww[jj] * f01.x;
                    acc.y += ww[jj] * f01.y;
                    acc.z += ww[jj] * f23.x;
                    acc.w += ww[jj] * f23.y;
                }
            }
        }

        {
            float* dst = &out[(size_t)r * D + lane * 4];
            asm volatile("st.global.cs.v4.f32 [%0], {%1,%2,%3,%4};"
                         :: "l"(dst), "f"(acc.x), "f"(acc.y), "f"(acc.z), "f"(acc.w)
                         : "memory");
        }

        if (with_stats) {
            ssum.x += acc.x; ssum.y += acc.y; ssum.z += acc.z; ssum.w += acc.w;
            ssq.x += acc.x * acc.x; ssq.y += acc.y * acc.y;
            ssq.z += acc.z * acc.z; ssq.w += acc.w * acc.w;
        }
    }

    if (with_stats) {
        atomicAdd(&s_st[lane * 4 + 0], ssum.x);
        atomicAdd(&s_st[lane * 4 + 1], ssum.y);
        atomicAdd(&s_st[lane * 4 + 2], ssum.z);
        atomicAdd(&s_st[lane * 4 + 3], ssum.w);
        atomicAdd(&s_st[D + lane * 4 + 0], ssq.x);
        atomicAdd(&s_st[D + lane * 4 + 1], ssq.y);
        atomicAdd(&s_st[D + lane * 4 + 2], ssq.z);
        atomicAdd(&s_st[D + lane * 4 + 3], ssq.w);
        __syncthreads();
        for (int i = threadIdx.x; i < 2 * D; i += 256)
            atomicAdd(&stats[i], s_st[i]);
    }
}

// ---------------- launch -----------------------------------------------------
extern "C" void kernel_launch(void* const* d_in, const int* in_sizes, int n_in,
                              void* d_out, int out_size)
{
    const float* x   = (const float*)d_in[0];
    const float* ew  = (const float*)d_in[1];
    const float* W0  = (const float*)d_in[2];
    const float* b0  = (const float*)d_in[3];
    const float* g0  = (const float*)d_in[4];
    const float* be0 = (const float*)d_in[5];
    const float* W1  = (const float*)d_in[6];
    const float* b1  = (const float*)d_in[7];
    const float* g1  = (const float*)d_in[8];
    const float* be1 = (const float*)d_in[9];
    const float* W2  = (const float*)d_in[10];
    const float* b2  = (const float*)d_in[11];
    const int*   row = (const int*)d_in[12];
    const int*   col = (const int*)d_in[13];
    float* out = (float*)d_out;

    int nrows  = in_sizes[0] / D;
    int nedges = in_sizes[1];
    float inv_n = 1.0f / (float)nrows;

    float  *hB, *stats;
    __half *hY;
    float2 *edges;
    int    *cnt;
    __nv_bfloat16 *wth, *wtl;
    cudaGetSymbolAddress((void**)&hY, g_hY);
    cudaGetSymbolAddress((void**)&hB, g_hB);
    cudaGetSymbolAddress((void**)&edges, g_edges);
    cudaGetSymbolAddress((void**)&cnt, g_cnt);
    cudaGetSymbolAddress((void**)&stats, g_stats);
    cudaGetSymbolAddress((void**)&wth, g_wt_hi);
    cudaGetSymbolAddress((void**)&wtl, g_wt_lo);

    const int SMEM_BYTES = 1024 + 2 * 128 * BSTRIDE * 2 + 2 * 128 * ASTRIDE * 2;
    cudaFuncSetAttribute(gemm_mma_kernel,
                         cudaFuncAttributeMaxDynamicSharedMemorySize, SMEM_BYTES);

    dim3 gemm_grid((nrows + 127) / 128);
    int  spmm_grid = 2048;

    prep_kernel<<<512, 256>>>(W0, W1, W2, wth, wtl, cnt, stats, nrows);
    scatter_kernel<<<(nedges + 255) / 256, 256>>>(row, col, ew, edges, cnt, nedges);

    // ---- layer 1 ----
    gemm_mma_kernel<<<gemm_grid, 256, SMEM_BYTES>>>(
        x, wth + 0 * D * D, wtl + 0 * D * D, b0,
        nullptr, nullptr, nullptr, inv_n, hY, nrows, 0);
    spmm_kernel<<<spmm_grid, 256>>>(cnt, edges, hY, hB, stats, nrows, 1);

    // ---- layer 2 (BN finalize + BN+ReLU fused into GEMM) ----
    gemm_mma_kernel<<<gemm_grid, 256, SMEM_BYTES>>>(
        hB, wth + 1 * D * D, wtl + 1 * D * D, b1,
        stats, g0, be0, inv_n, hY, nrows, 1);
    spmm_kernel<<<spmm_grid, 256>>>(cnt, edges, hY, hB, stats + 2 * D, nrows, 1);

    // ---- layer 3 ----
    gemm_mma_kernel<<<gemm_grid, 256, SMEM_BYTES>>>(
        hB, wth + 2 * D * D, wtl + 2 * D * D, b2,
        stats + 2 * D, g1, be1, inv_n, hY, nrows, 1);
    spmm_kernel<<<spmm_grid, 256>>>(cnt, edges, hY, out, nullptr, nrows, 0);
}

// round 14
// speedup vs baseline: 1.2945x; 1.0781x over previous
#include <cuda_runtime.h>
#include <cuda_bf16.h>
#include <cuda_fp16.h>
#include <cstdint>
#include <cstddef>

#define D 128
#define EPS_BN 1e-5f
#define MAX_NODES 100000
#define CAP 96
#define BSTRIDE 136      // B smem row stride in bf16 (68 words: conflict-free)
#define ASTRIDE 72       // A smem row stride in bf16 (36 words: conflict-free)

// ---------------- scratch (__device__ globals; allocation-free rule) --------
__device__ __half g_hY[(size_t)MAX_NODES * D];     // GEMM output (fp16), SpMM gather src
__device__ float  g_hB[(size_t)MAX_NODES * D];     // SpMM output (fp32), GEMM input
__device__ float2 g_edges[(size_t)MAX_NODES * CAP];
__device__ int    g_cnt[MAX_NODES];
__device__ float  g_stats[4 * D];
__device__ __nv_bfloat16 g_wt_hi[3][D * D];   // W^T split-hi, [n][k]
__device__ __nv_bfloat16 g_wt_lo[3][D * D];   // W^T split-lo, [n][k]

// ---------------- helpers -----------------------------------------------------
__device__ __forceinline__ uint32_t smem_u32(const void* p) {
    uint32_t a;
    asm("{ .reg .u64 t; cvta.to.shared.u64 t, %1; cvt.u32.u64 %0, t; }"
        : "=r"(a) : "l"(p));
    return a;
}
#define LDSM_X4(r0, r1, r2, r3, addr) \
    asm volatile("ldmatrix.sync.aligned.m8n8.x4.shared.b16 {%0,%1,%2,%3}, [%4];" \
        : "=r"(r0), "=r"(r1), "=r"(r2), "=r"(r3) : "r"(addr))

// ---------------- prep: zero cnt/stats + W transpose/split (one launch) -----
__global__ void prep_kernel(const float* __restrict__ W0, const float* __restrict__ W1,
                            const float* __restrict__ W2,
                            __nv_bfloat16* __restrict__ th, __nv_bfloat16* __restrict__ tl,
                            int* __restrict__ cnt, float* __restrict__ stats, int n) {
    int i = blockIdx.x * blockDim.x + threadIdx.x;
    int stride = gridDim.x * blockDim.x;
    for (int j = i; j < n; j += stride) cnt[j] = 0;
    if (i < 4 * D) stats[i] = 0.0f;
    for (int j = i; j < 3 * D * D; j += stride) {
        int layer = j >> 14;
        int idx   = j & (D * D - 1);
        const float* W = (layer == 0) ? W0 : (layer == 1) ? W1 : W2;
        int nn = idx & 127, k = idx >> 7;
        float v = W[idx];
        __nv_bfloat16 h = __float2bfloat16(v);
        float r = v - __bfloat162float(h);
        th[layer * D * D + nn * D + k] = h;
        tl[layer * D * D + nn * D + k] = __float2bfloat16(r);
    }
}

// ---------------- scatter edges into per-row buckets ------------------------
__global__ void scatter_kernel(const int* __restrict__ row, const int* __restrict__ col,
                               const float* __restrict__ w, float2* __restrict__ edges,
                               int* __restrict__ cnt, int nedges) {
    int e = blockIdx.x * blockDim.x + threadIdx.x;
    if (e >= nedges) return;
    int r = row[e];
    int slot = atomicAdd(&cnt[r], 1);
    if (slot < CAP)
        edges[(size_t)r * CAP + slot] = make_float2(__int_as_float(col[e]), w[e]);
}

// ---------------- warp-tile MMA ----------------------------------------------
__device__ __forceinline__ void mma16816(float* c, const uint32_t* a, const uint32_t* b) {
    asm volatile(
        "mma.sync.aligned.m16n8k16.row.col.f32.bf16.bf16.f32 "
        "{%0,%1,%2,%3}, {%4,%5,%6,%7}, {%8,%9}, {%0,%1,%2,%3};"
        : "+f"(c[0]), "+f"(c[1]), "+f"(c[2]), "+f"(c[3])
        : "r"(a[0]), "r"(a[1]), "r"(a[2]), "r"(a[3]), "r"(b[0]), "r"(b[1]));
}

// truncation split of 2 floats -> (hi bf16x2, lo bf16x2)
__device__ __forceinline__ void split2(float vx, float vy, uint32_t& hi2, uint32_t& lo2) {
    uint32_t bx = __float_as_uint(vx) & 0xffff0000u;
    uint32_t by = __float_as_uint(vy) & 0xffff0000u;
    hi2 = __byte_perm(bx, by, 0x7632);
    float lx = vx - __uint_as_float(bx);
    float ly = vy - __uint_as_float(by);
    __nv_bfloat162 l = __floats2bfloat162_rn(lx, ly);
    lo2 = *(uint32_t*)&l;
}

// GEMM: Y(fp16) = act(X) @ W + b; act = relu(bn) from raw column stats.
__global__ __launch_bounds__(256, 2) void gemm_mma_kernel(
    const float* __restrict__ X,
    const __nv_bfloat16* __restrict__ Wt_hi, const __nv_bfloat16* __restrict__ Wt_lo,
    const float* __restrict__ bias,
    const float* __restrict__ stats,
    const float* __restrict__ gamma, const float* __restrict__ beta,
    float inv_n,
    __half* __restrict__ Y, int nrows, int use_bn)
{
    extern __shared__ __align__(16) char dsm[];
    float* s_scale = (float*)dsm;
    float* s_shift = s_scale + D;
    __nv_bfloat16* Bh = (__nv_bfloat16*)(dsm + 1024);
    __nv_bfloat16* Bl = Bh + 128 * BSTRIDE;
    __nv_bfloat16* Ah = Bl + 128 * BSTRIDE;
    __nv_bfloat16* Al = Ah + 128 * ASTRIDE;

    int t = threadIdx.x, lane = t & 31, wid = t >> 5;
    int row0 = blockIdx.x * 128;
    int g = lane >> 2, tg = lane & 3;

    if (use_bn && t < D) {
        float m   = stats[t] * inv_n;
        float var = stats[D + t] * inv_n - m * m;
        float rs  = rsqrtf(var + EPS_BN);
        float sc  = gamma[t] * rs;
        s_scale[t] = sc;
        s_shift[t] = beta[t] - m * sc;
    }

    for (int i = t; i < 2048; i += 256) {
        int n  = i >> 4;
        int c8 = i & 15;
        *(uint4*)&Bh[n * BSTRIDE + c8 * 8] = *(const uint4*)&Wt_hi[n * D + c8 * 8];
        *(uint4*)&Bl[n * BSTRIDE + c8 * 8] = *(const uint4*)&Wt_lo[n * D + c8 * 8];
    }

    int m0 = (wid & 1) * 64;
    int n0 = (wid >> 1) * 32;

    int a_row_local = ((lane >> 3) & 1) * 8 + (lane & 7);
    int a_colh      = (lane >> 4) * 8;
    int b_row_local = ((lane >> 4) & 1) * 8 + (lane & 7);
    int b_colh      = ((lane >> 3) & 1) * 8;

    uint32_t aoffs[4], boffs[2];
#pragma unroll
    for (int mt = 0; mt < 4; mt++)
        aoffs[mt] = (uint32_t)(((m0 + mt * 16 + a_row_local) * ASTRIDE + a_colh) * 2);
#pragma unroll
    for (int ntp = 0; ntp < 2; ntp++)
        boffs[ntp] = (uint32_t)(((n0 + ntp * 16 + b_row_local) * BSTRIDE + b_colh) * 2);

    uint32_t ah_b = smem_u32(Ah), al_b = smem_u32(Al);
    uint32_t bh_b = smem_u32(Bh), bl_b = smem_u32(Bl);

    float acc[4][4][4];
#pragma unroll
    for (int mt = 0; mt < 4; mt++)
#pragma unroll
        for (int nt = 0; nt < 4; nt++)
#pragma unroll
            for (int j = 0; j < 4; j++) acc[mt][nt][j] = 0.0f;

    __syncthreads();

#pragma unroll
    for (int kh = 0; kh < 2; kh++) {
        for (int i = t; i < 2048; i += 256) {
            int r  = i >> 4;
            int f4 = i & 15;
            int col0 = kh * 64 + f4 * 4;
            int row = row0 + r;
            float4 v = make_float4(0.f, 0.f, 0.f, 0.f);
            if (row < nrows) {
                v = *(const float4*)&X[(size_t)row * D + col0];
                if (use_bn) {
                    v.x = fmaxf(fmaf(v.x, s_scale[col0 + 0], s_shift[col0 + 0]), 0.0f);
                    v.y = fmaxf(fmaf(v.y, s_scale[col0 + 1], s_shift[col0 + 1]), 0.0f);
                    v.z = fmaxf(fmaf(v.z, s_scale[col0 + 2], s_shift[col0 + 2]), 0.0f);
                    v.w = fmaxf(fmaf(v.w, s_scale[col0 + 3], s_shift[col0 + 3]), 0.0f);
                }
            }
            uint2 ph, pl;
            split2(v.x, v.y, ph.x, pl.x);
            split2(v.z, v.w, ph.y, pl.y);
            *(uint2*)&Ah[r * ASTRIDE + f4 * 4] = ph;
            *(uint2*)&Al[r * ASTRIDE + f4 * 4] = pl;
        }
        __syncthreads();

#pragma unroll
        for (int pass = 0; pass < 3; pass++) {
            uint32_t abase = (pass < 2) ? ah_b : al_b;
            uint32_t bbase = ((pass == 1) ? bl_b : bh_b) + (uint32_t)(kh * 64 * 2);
#pragma unroll
            for (int ks = 0; ks < 4; ks++) {
                uint32_t kso = (uint32_t)(ks * 32);
                uint32_t a[4][4];
#pragma unroll
                for (int mt = 0; mt < 4; mt++)
                    LDSM_X4(a[mt][0], a[mt][1], a[mt][2], a[mt][3],
                            abase + aoffs[mt] + kso);
                uint32_t b[2][4];
#pragma unroll
                for (int ntp = 0; ntp < 2; ntp++)
                    LDSM_X4(b[ntp][0], b[ntp][1], b[ntp][2], b[ntp][3],
                            bbase + boffs[ntp] + kso);
#pragma unroll
                for (int mt = 0; mt < 4; mt++)
#pragma unroll
                    for (int nt = 0; nt < 4; nt++)
                        mma16816(acc[mt][nt], a[mt], &b[nt >> 1][(nt & 1) * 2]);
            }
        }
        __syncthreads();
    }

    float2 bv[4];
#pragma unroll
    for (int nt = 0; nt < 4; nt++) {
        int cidx = n0 + nt * 8 + tg * 2;
        bv[nt] = *(const float2*)&bias[cidx];
    }
#pragma unroll
    for (int mt = 0; mt < 4; mt++) {
        int ra = row0 + m0 + mt * 16 + g;
        int rb = ra + 8;
#pragma unroll
        for (int nt = 0; nt < 4; nt++) {
            int cidx = n0 + nt * 8 + tg * 2;
            if (ra < nrows) {
                __half2 o = __floats2half2_rn(acc[mt][nt][0] + bv[nt].x,
                                              acc[mt][nt][1] + bv[nt].y);
                *(__half2*)&Y[(size_t)ra * D + cidx] = o;
            }
            if (rb < nrows) {
                __half2 o = __floats2half2_rn(acc[mt][nt][2] + bv[nt].x,
                                              acc[mt][nt][3] + bv[nt].y);
                *(__half2*)&Y[(size_t)rb * D + cidx] = o;
            }
        }
    }
}

// ---------------- SpMM: warp/row, smem edge broadcast, u32 offsets ----------
__global__ __launch_bounds__(256) void spmm_kernel(
    const int* __restrict__ cnt, const float2* __restrict__ edges,
    const __half* __restrict__ H, float* __restrict__ out,
    float* __restrict__ stats, int nrows, int with_stats)
{
    __shared__ float  s_st[2 * D];
    __shared__ float2 s_edge[8][32];

    int lane = threadIdx.x & 31;
    int wl   = threadIdx.x >> 5;
    int warp = blockIdx.x * 8 + wl;
    int nwarp = gridDim.x * 8;

    if (with_stats) {
        for (int i = threadIdx.x; i < 2 * D; i += 256) s_st[i] = 0.0f;
        __syncthreads();
    }

    // per-lane base pointer: H + lane*4 halves (8 bytes)
    const char* Hl = (const char*)H + lane * 8;

    float4 ssum = make_float4(0.f, 0.f, 0.f, 0.f);
    float4 ssq  = make_float4(0.f, 0.f, 0.f, 0.f);

    for (int r = warp; r < nrows; r += nwarp) {
        int deg = __ldg(&cnt[r]);
        const float2* bucket = &edges[(size_t)r * CAP];
        float4 acc = make_float4(0.f, 0.f, 0.f, 0.f);

        for (int base = 0; base < deg; base += 32) {
            // stage up to 32 edge records in smem (pad: col 0, weight 0)
            float2 e = make_float2(0.0f, 0.0f);
            if (base + lane < deg) e = bucket[base + lane];
            s_edge[wl][lane] = e;
            __syncwarp();

            int m = min(32, deg - base);
            for (int b2 = 0; b2 < m; b2 += 8) {
                uint32_t off[8];
                float    ww[8];
#pragma unroll
                for (int jj = 0; jj < 8; jj++) {
                    float2 ee = s_edge[wl][b2 + jj];        // LDS.64 broadcast
                    off[jj] = (uint32_t)__float_as_int(ee.x) << 8;  // col * 256B
                    ww[jj]  = ee.y;
                }
                uint2 v[8];
#pragma unroll
                for (int jj = 0; jj < 8; jj++)
                    v[jj] = *(const uint2*)(Hl + off[jj]);   // 8 independent gathers
#pragma unroll
                for (int jj = 0; jj < 8; jj++) {
                    float2 f01 = __half22float2(*(__half2*)&v[jj].x);
                    float2 f23 = __half22float2(*(__half2*)&v[jj].y);
                    acc.x += ww[jj] * f01.x;
                    acc.y += ww[jj] * f01.y;
                    acc.z += ww[jj] * f23.x;
                    acc.w += ww[jj] * f23.y;
                }
            }
            __syncwarp();   // before next batch overwrites s_edge
        }

        {
            float* dst = &out[(size_t)r * D + lane * 4];
            asm volatile("st.global.cs.v4.f32 [%0], {%1,%2,%3,%4};"
                         :: "l"(dst), "f"(acc.x), "f"(acc.y), "f"(acc.z), "f"(acc.w)
                         : "memory");
        }

        if (with_stats) {
            ssum.x += acc.x; ssum.y += acc.y; ssum.z += acc.z; ssum.w += acc.w;
            ssq.x += acc.x * acc.x; ssq.y += acc.y * acc.y;
            ssq.z += acc.z * acc.z; ssq.w += acc.w * acc.w;
        }
    }

    if (with_stats) {
        atomicAdd(&s_st[lane * 4 + 0], ssum.x);
        atomicAdd(&s_st[lane * 4 + 1], ssum.y);
        atomicAdd(&s_st[lane * 4 + 2], ssum.z);
        atomicAdd(&s_st[lane * 4 + 3], ssum.w);
        atomicAdd(&s_st[D + lane * 4 + 0], ssq.x);
        atomicAdd(&s_st[D + lane * 4 + 1], ssq.y);
        atomicAdd(&s_st[D + lane * 4 + 2], ssq.z);
        atomicAdd(&s_st[D + lane * 4 + 3], ssq.w);
        __syncthreads();
        for (int i = threadIdx.x; i < 2 * D; i += 256)
            atomicAdd(&stats[i], s_st[i]);
    }
}

// ---------------- launch -----------------------------------------------------
extern "C" void kernel_launch(void* const* d_in, const int* in_sizes, int n_in,
                              void* d_out, int out_size)
{
    const float* x   = (const float*)d_in[0];
    const float* ew  = (const float*)d_in[1];
    const float* W0  = (const float*)d_in[2];
    const float* b0  = (const float*)d_in[3];
    const float* g0  = (const float*)d_in[4];
    const float* be0 = (const float*)d_in[5];
    const float* W1  = (const float*)d_in[6];
    const float* b1  = (const float*)d_in[7];
    const float* g1  = (const float*)d_in[8];
    const float* be1 = (const float*)d_in[9];
    const float* W2  = (const float*)d_in[10];
    const float* b2  = (const float*)d_in[11];
    const int*   row = (const int*)d_in[12];
    const int*   col = (const int*)d_in[13];
    float* out = (float*)d_out;

    int nrows  = in_sizes[0] / D;
    int nedges = in_sizes[1];
    float inv_n = 1.0f / (float)nrows;

    float  *hB, *stats;
    __half *hY;
    float2 *edges;
    int    *cnt;
    __nv_bfloat16 *wth, *wtl;
    cudaGetSymbolAddress((void**)&hY, g_hY);
    cudaGetSymbolAddress((void**)&hB, g_hB);
    cudaGetSymbolAddress((void**)&edges, g_edges);
    cudaGetSymbolAddress((void**)&cnt, g_cnt);
    cudaGetSymbolAddress((void**)&stats, g_stats);
    cudaGetSymbolAddress((void**)&wth, g_wt_hi);
    cudaGetSymbolAddress((void**)&wtl, g_wt_lo);

    const int SMEM_BYTES = 1024 + 2 * 128 * BSTRIDE * 2 + 2 * 128 * ASTRIDE * 2;
    cudaFuncSetAttribute(gemm_mma_kernel,
                         cudaFuncAttributeMaxDynamicSharedMemorySize, SMEM_BYTES);

    dim3 gemm_grid((nrows + 127) / 128);
    int  spmm_grid = 2048;

    prep_kernel<<<512, 256>>>(W0, W1, W2, wth, wtl, cnt, stats, nrows);
    scatter_kernel<<<(nedges + 255) / 256, 256>>>(row, col, ew, edges, cnt, nedges);

    // ---- layer 1 ----
    gemm_mma_kernel<<<gemm_grid, 256, SMEM_BYTES>>>(
        x, wth + 0 * D * D, wtl + 0 * D * D, b0,
        nullptr, nullptr, nullptr, inv_n, hY, nrows, 0);
    spmm_kernel<<<spmm_grid, 256>>>(cnt, edges, hY, hB, stats, nrows, 1);

    // ---- layer 2 (BN finalize + BN+ReLU fused into GEMM) ----
    gemm_mma_kernel<<<gemm_grid, 256, SMEM_BYTES>>>(
        hB, wth + 1 * D * D, wtl + 1 * D * D, b1,
        stats, g0, be0, inv_n, hY, nrows, 1);
    spmm_kernel<<<spmm_grid, 256>>>(cnt, edges, hY, hB, stats + 2 * D, nrows, 1);

    // ---- layer 3 ----
    gemm_mma_kernel<<<gemm_grid, 256, SMEM_BYTES>>>(
        hB, wth + 2 * D * D, wtl + 2 * D * D, b2,
        stats + 2 * D, g1, be1, inv_n, hY, nrows, 1);
    spmm_kernel<<<spmm_grid, 256>>>(cnt, edges, hY, out, nullptr, nrows, 0);
}